// round 2
// baseline (speedup 1.0000x reference)
#include <cuda_runtime.h>
#include <cstddef>

// ODE-RNN persistent kernel.
// T=500 steps, B=4096 rows, INPUT_DIM=32, HIDDEN=16, ODE_HIDDEN=50 (padded 56), RK4 x4 substeps.
// Each row is handled by 8 lanes (4 rows per warp, 16 rows per 128-thread block).
// Hidden state replicated across the 8 lanes of a row group.

#define T_STEPS 500
#define BATCH   4096
#define IN_DIM  32
#define HID     16
#define PHID    50
#define PPAD    56   // padded ODE hidden (7 per lane * 8 lanes)
#define W2PITCH 17   // padded row pitch for conflict-free LDS
#define BLK     128  // threads per block
#define ROWS_PER_BLK (BLK / 8)

struct SW {
    float W1T[HID * PPAD];    // W1T[k*PPAD + j] = W1[j][k], zero-padded j>=50
    float b1[PPAD];           // zero-padded
    float W2[PPAD * W2PITCH]; // W2[j*17 + i] = W2[i][j], zero-padded
    float b2[HID];
    float Wih[IN_DIM * 48];   // Wih[m*48 + c] = W_ih[c][m]
    float bih[48];
    float Whh[HID * 48];      // Whh[k*48 + c] = W_hh[c][k]
    float bhh[48];
    float Wout[HID];
    float bout;
    float ts[T_STEPS];
};

__device__ __forceinline__ float fast_tanh(float v) {
    float e = __expf(2.0f * v);
    return 1.0f - __fdividef(2.0f, e + 1.0f);
}
__device__ __forceinline__ float fast_sig(float v) {
    return __fdividef(1.0f, 1.0f + __expf(-v));
}

// f = W2 * tanh(W1 * y + b1) + b2, y replicated in regs on all 8 lanes of the group.
// Result f replicated on all 8 lanes.
__device__ __forceinline__ void ode_f(const SW& s, const float (&y)[HID], float (&f)[HID], int lane) {
    float z[7];
#pragma unroll
    for (int jj = 0; jj < 7; jj++) {
        const int j = lane + jj * 8;
        float a = s.b1[j];
#pragma unroll
        for (int k = 0; k < HID; k++)
            a = fmaf(y[k], s.W1T[k * PPAD + j], a);
        z[jj] = fast_tanh(a);
    }
    float pf[HID];
#pragma unroll
    for (int i = 0; i < HID; i++) pf[i] = 0.0f;
#pragma unroll
    for (int jj = 0; jj < 7; jj++) {
        const int j = lane + jj * 8;
#pragma unroll
        for (int i = 0; i < HID; i++)
            pf[i] = fmaf(z[jj], s.W2[j * W2PITCH + i], pf[i]);
    }
    // all-reduce across the 8 lanes of the row group
#pragma unroll
    for (int i = 0; i < HID; i++) {
        float v = pf[i];
        v += __shfl_xor_sync(0xffffffffu, v, 1, 8);
        v += __shfl_xor_sync(0xffffffffu, v, 2, 8);
        v += __shfl_xor_sync(0xffffffffu, v, 4, 8);
        f[i] = v + s.b2[i];
    }
}

__global__ void __launch_bounds__(BLK) odernn_kernel(
    const float* __restrict__ x,   const float* __restrict__ t,
    const float* __restrict__ W1,  const float* __restrict__ b1,
    const float* __restrict__ W2,  const float* __restrict__ b2,
    const float* __restrict__ Wih, const float* __restrict__ bih,
    const float* __restrict__ Whh, const float* __restrict__ bhh,
    const float* __restrict__ Wout, const float* __restrict__ bout,
    float* __restrict__ out)
{
    __shared__ SW s;
    const int tid = threadIdx.x;

    // ---- stage weights (transposed / padded) into shared ----
    for (int idx = tid; idx < HID * PPAD; idx += BLK) {
        int k = idx / PPAD, j = idx % PPAD;
        s.W1T[idx] = (j < PHID) ? W1[j * HID + k] : 0.0f;
    }
    for (int idx = tid; idx < PPAD; idx += BLK) s.b1[idx] = (idx < PHID) ? b1[idx] : 0.0f;
    for (int idx = tid; idx < PPAD * W2PITCH; idx += BLK) {
        int j = idx / W2PITCH, i = idx % W2PITCH;
        s.W2[idx] = (j < PHID && i < HID) ? W2[i * PHID + j] : 0.0f;
    }
    for (int idx = tid; idx < HID; idx += BLK) s.b2[idx] = b2[idx];
    for (int idx = tid; idx < IN_DIM * 48; idx += BLK) {
        int m = idx / 48, c = idx % 48;
        s.Wih[idx] = Wih[c * IN_DIM + m];
    }
    for (int idx = tid; idx < 48; idx += BLK) s.bih[idx] = bih[idx];
    for (int idx = tid; idx < HID * 48; idx += BLK) {
        int k = idx / 48, c = idx % 48;
        s.Whh[idx] = Whh[c * HID + k];
    }
    for (int idx = tid; idx < 48; idx += BLK) s.bhh[idx] = bhh[idx];
    for (int idx = tid; idx < HID; idx += BLK) s.Wout[idx] = Wout[idx];
    if (tid == 0) s.bout = bout[0];
    for (int idx = tid; idx < T_STEPS; idx += BLK) s.ts[idx] = t[idx];
    __syncthreads();

    const int lane = tid & 7;       // lane within the 8-lane row group
    const int grp  = tid >> 3;      // 0..15 : row within the block
    const int row  = blockIdx.x * ROWS_PER_BLK + grp;
    const int u1 = lane, u2 = lane + 8;   // GRU units this lane owns

    float h[HID], y[HID], acc[HID], f[HID];
#pragma unroll
    for (int k = 0; k < HID; k++) h[k] = 0.0f;

#pragma unroll 1
    for (int i = 0; i < T_STEPS - 1; ++i) {
        // ---- prefetch this step's input row (used at the end, in the GRU) ----
        float xr[IN_DIM];
        const float4* xp = reinterpret_cast<const float4*>(x + ((size_t)i * BATCH + row) * IN_DIM);
#pragma unroll
        for (int qv = 0; qv < IN_DIM / 4; qv++) {
            float4 v = __ldg(xp + qv);
            xr[4 * qv + 0] = v.x; xr[4 * qv + 1] = v.y;
            xr[4 * qv + 2] = v.z; xr[4 * qv + 3] = v.w;
        }

        const float dt  = (s.ts[i + 1] - s.ts[i]) * 0.25f;  // substep dt
        const float hdt = 0.5f * dt;
        const float dt6 = dt / 6.0f;

        // ---- 4 RK4 substeps ----
#pragma unroll 1
        for (int ss = 0; ss < 4; ss++) {
#pragma unroll
            for (int k = 0; k < HID; k++) y[k] = h[k];
#pragma unroll 1
            for (int e = 0; e < 4; e++) {
                ode_f(s, y, f, lane);
                const float w  = (e == 0 || e == 3) ? 1.0f : 2.0f;
                const float cy = (e == 2) ? dt : hdt;
                if (e == 0) {
#pragma unroll
                    for (int k = 0; k < HID; k++) acc[k] = f[k];
                } else {
#pragma unroll
                    for (int k = 0; k < HID; k++) acc[k] = fmaf(w, f[k], acc[k]);
                }
                if (e < 3) {
#pragma unroll
                    for (int k = 0; k < HID; k++) y[k] = fmaf(cy, f[k], h[k]);
                }
            }
#pragma unroll
            for (int k = 0; k < HID; k++) h[k] = fmaf(dt6, acc[k], h[k]);
        }

        // ---- GRU cell (gate order r, z, n). Lane computes units u1, u2. ----
        float g[6], q[6];
#pragma unroll
        for (int e = 0; e < 3; e++) {
            g[e]     = s.bih[e * 16 + u1];
            g[3 + e] = s.bih[e * 16 + u2];
            q[e]     = s.bhh[e * 16 + u1];
            q[3 + e] = s.bhh[e * 16 + u2];
        }
#pragma unroll
        for (int m = 0; m < IN_DIM; m++) {
            const float xv = xr[m];
#pragma unroll
            for (int e = 0; e < 3; e++) {
                g[e]     = fmaf(xv, s.Wih[m * 48 + e * 16 + u1], g[e]);
                g[3 + e] = fmaf(xv, s.Wih[m * 48 + e * 16 + u2], g[3 + e]);
            }
        }
        float hu1 = 0.0f, hu2 = 0.0f;
#pragma unroll
        for (int k = 0; k < HID; k++) {
            const float hk = h[k];
            if (k < 8)  { if (k == u1) hu1 = hk; }
            else        { if (k == u2) hu2 = hk; }
#pragma unroll
            for (int e = 0; e < 3; e++) {
                q[e]     = fmaf(hk, s.Whh[k * 48 + e * 16 + u1], q[e]);
                q[3 + e] = fmaf(hk, s.Whh[k * 48 + e * 16 + u2], q[3 + e]);
            }
        }
        const float r1 = fast_sig(g[0] + q[0]);
        const float z1 = fast_sig(g[1] + q[1]);
        const float n1 = fast_tanh(fmaf(r1, q[2], g[2]));
        const float hn1 = fmaf(z1, hu1 - n1, n1);   // (1-z)*n + z*h
        const float r2 = fast_sig(g[3] + q[3]);
        const float z2 = fast_sig(g[4] + q[4]);
        const float n2 = fast_tanh(fmaf(r2, q[5], g[5]));
        const float hn2 = fmaf(z2, hu2 - n2, n2);

        // ---- output head: out = h_new . Wout + bout ----
        float po = hn1 * s.Wout[u1] + hn2 * s.Wout[u2];
        po += __shfl_xor_sync(0xffffffffu, po, 1, 8);
        po += __shfl_xor_sync(0xffffffffu, po, 2, 8);
        po += __shfl_xor_sync(0xffffffffu, po, 4, 8);
        if (lane == 0) out[(size_t)i * BATCH + row] = po + s.bout;

        // ---- replicate new hidden state to all 8 lanes ----
#pragma unroll
        for (int k = 0; k < 8; k++) {
            h[k]     = __shfl_sync(0xffffffffu, hn1, k, 8);
            h[k + 8] = __shfl_sync(0xffffffffu, hn2, k, 8);
        }
    }
}

extern "C" void kernel_launch(void* const* d_in, const int* in_sizes, int n_in,
                              void* d_out, int out_size) {
    (void)in_sizes; (void)n_in; (void)out_size;
    const float* x    = (const float*)d_in[0];
    const float* t    = (const float*)d_in[1];
    const float* W1   = (const float*)d_in[2];
    const float* b1   = (const float*)d_in[3];
    const float* W2   = (const float*)d_in[4];
    const float* b2   = (const float*)d_in[5];
    const float* Wih  = (const float*)d_in[6];
    const float* bih  = (const float*)d_in[7];
    const float* Whh  = (const float*)d_in[8];
    const float* bhh  = (const float*)d_in[9];
    const float* Wout = (const float*)d_in[10];
    const float* bout = (const float*)d_in[11];
    float* out = (float*)d_out;

    dim3 grid(BATCH / ROWS_PER_BLK);   // 16 rows per 128-thread block (8 lanes per row)
    dim3 block(BLK);
    odernn_kernel<<<grid, block>>>(x, t, W1, b1, W2, b2, Wih, bih, Whh, bhh, Wout, bout, out);
}